// round 14
// baseline (speedup 1.0000x reference)
#include <cuda_runtime.h>
#include <cuda_fp16.h>
#include <math.h>
#include <stdint.h>

#define MTOK 50176
#define CCH 384
#define HWN 3136
#define PI_F 3.14159265358979323846f

// ---------------- scratch ----------------
__device__ float g_xt[(size_t)MTOK * CCH];
__device__ float g_xg[(size_t)MTOK * CCH];
__device__ float g_z [(size_t)MTOK * CCH];
__device__ float g_t1[(size_t)MTOK * CCH];
__device__ float g_u0[(size_t)MTOK * CCH];
__device__ float g_v0[(size_t)MTOK * CCH];
__device__ float g_cosb[(size_t)HWN * CCH];
__device__ float g_sinb[(size_t)HWN * CCH];
__device__ float g_D[56 * 56];
__device__ __half g_wlh[768 * 384];
__device__ __half g_wvh[384 * 384];
__device__ __half g_woh[384 * 384];
__device__ __half g_wth[384 * 384];

__device__ __forceinline__ unsigned f2tf32(float x) {
    unsigned r;
    asm("cvt.rna.tf32.f32 %0, %1;" : "=r"(r) : "f"(x));
    return r;
}
__device__ __forceinline__ float round_tf32(float x) {
    return __uint_as_float(f2tf32(x));
}
__device__ __forceinline__ uint32_t smem_u32(const void* p) {
    uint32_t a;
    asm("{ .reg .u64 t; cvta.to.shared.u64 t, %1; cvt.u32.u64 %0, t; }" : "=r"(a) : "l"(p));
    return a;
}
#define CP16(smaddr, gptr) \
    asm volatile("cp.async.ca.shared.global [%0], [%1], 16;" :: "r"(smaddr), "l"(gptr))

#define MMA_T(acc, a0, a1, a2, a3, b0, b1) \
    asm volatile( \
        "mma.sync.aligned.m16n8k8.row.col.f32.tf32.tf32.f32 " \
        "{%0,%1,%2,%3}, {%4,%5,%6,%7}, {%8,%9}, {%0,%1,%2,%3};" \
        : "+f"((acc)[0]), "+f"((acc)[1]), "+f"((acc)[2]), "+f"((acc)[3]) \
        : "r"(a0), "r"(a1), "r"(a2), "r"(a3), "r"(b0), "r"(b1))

#define MMA_H(acc, a0, a1, a2, a3, b0, b1) \
    asm volatile( \
        "mma.sync.aligned.m16n8k16.row.col.f32.f16.f16.f32 " \
        "{%0,%1,%2,%3}, {%4,%5,%6,%7}, {%8,%9}, {%0,%1,%2,%3};" \
        : "+f"((acc)[0]), "+f"((acc)[1]), "+f"((acc)[2]), "+f"((acc)[3]) \
        : "r"(a0), "r"(a1), "r"(a2), "r"(a3), "r"(b0), "r"(b1))

#define LDSM_X4(r0, r1, r2, r3, addr) \
    asm volatile("ldmatrix.sync.aligned.m8n8.x4.shared.b16 {%0,%1,%2,%3}, [%4];" \
        : "=r"(r0), "=r"(r1), "=r"(r2), "=r"(r3) : "r"(addr))

// non-trans: B stored [n][k]; lane i gets B[n=i/4][k=2(i%4)..] = exact mma b-fragment
#define LDSM_X2(r0, r1, addr) \
    asm volatile("ldmatrix.sync.aligned.m8n8.x2.shared.b16 {%0,%1}, [%2];" \
        : "=r"(r0), "=r"(r1) : "r"(addr))

// ---------------- weight pre-convert to fp16 ----------------
__global__ void cvtw_h(const float* __restrict__ in, __half* __restrict__ out, int n) {
    int i = blockIdx.x * 256 + threadIdx.x;
    if (i < n) out[i] = __float2half_rn(in[i]);
}

// ---------------- DCT matrix init ----------------
__global__ void dct_init_k(float* D) {
    int idx = blockIdx.x * 256 + threadIdx.x;
    if (idx < 56 * 56) {
        int k = idx / 56, n = idx % 56;
        double v = cos(3.14159265358979323846 * (2.0 * n + 1.0) * k / 112.0) * sqrt(2.0 / 56.0);
        if (k == 0) v *= (1.0 / sqrt(2.0));
        D[idx] = (float)v;
    }
}

// ---------------- depthwise 3x3 conv -> token-major fp16 ----------------
__global__ void dwconv_k(const float* __restrict__ x, const float* __restrict__ w,
                         const float* __restrict__ bias, __half* __restrict__ xt) {
    __shared__ float s[8][33];
    int tx = threadIdx.x, ty = threadIdx.y;
    int wseg = blockIdx.x & 1;
    int h = blockIdx.x >> 1;
    int c = blockIdx.y * 8 + ty;
    int b = blockIdx.z;
    int ww = wseg * 32 + tx;

    if (ww < 56) {
        float acc = bias[c];
        const float* xp = x + ((size_t)(b * CCH + c) * 56) * 56;
        const float* wp = w + c * 9;
        #pragma unroll
        for (int kh = 0; kh < 3; kh++) {
            int hh = h + kh - 1;
            if (hh < 0 || hh >= 56) continue;
            #pragma unroll
            for (int kw = 0; kw < 3; kw++) {
                int wc = ww + kw - 1;
                if (wc < 0 || wc >= 56) continue;
                acc += xp[hh * 56 + wc] * wp[kh * 3 + kw];
            }
        }
        s[ty][tx] = acc;
    }
    __syncthreads();
    int tid = ty * 32 + tx;
    int wi = tid >> 3, ci = tid & 7;
    int wo = wseg * 32 + wi;
    if (wo < 56) {
        int cout = blockIdx.y * 8 + ci;
        size_t tok = (size_t)b * HWN + h * 56 + wo;
        xt[tok * CCH + cout] = __float2half_rn(s[ci][wi]);
    }
}

// ---------------- FP16 TC GEMM: 8 warps x (64x32), ldmatrix, cp.async 3-stage ----------------
// A[M][K], Wt[N][K] fp16 (pre-converted). Smem rows padded to 24 halves (48B).
// EPI 0: +bias split -> O0/O1 ; 1: +bias -> O0 ; 2: wave mod ; 3: +bias transposed NCHW ;
// EPI 4: +bias relu cos/sin (U = cptr, rows guarded to HWN)
#define TBM 128
#define TBN 128
#define NST 3
#define HP 24                 // halves per smem row (48B)
#define STGB (128 * 48)       // bytes per stage per matrix

template <int EPI>
__global__ void __launch_bounds__(256, 2) gemm_tc(
    const __half* __restrict__ A, const __half* __restrict__ Wt,
    const float* __restrict__ bias,
    float* __restrict__ O0, float* __restrict__ O1,
    const float* __restrict__ U, const float* __restrict__ cosb,
    const float* __restrict__ sinb, const float* __restrict__ velb,
    const float* __restrict__ alphap,
    int M, int N, int K) {
    __shared__ __align__(16) __half As[NST][TBM][HP];
    __shared__ __align__(16) __half Bs[NST][TBN][HP];

    int tid = threadIdx.x;
    int lane = tid & 31;
    int warp = tid >> 5;
    int wm = warp & 1;
    int wn = warp >> 1;
    int m0 = blockIdx.y * TBM;
    int n0 = blockIdx.x * TBN;
    int grp = lane >> 2;
    int qd = lane & 3;

    float acc[4][4][4];
    #pragma unroll
    for (int i = 0; i < 4; i++)
        #pragma unroll
        for (int j = 0; j < 4; j++)
            #pragma unroll
            for (int r = 0; r < 4; r++) acc[i][j][r] = 0.f;

    // cp.async: 256 chunks of 16B (8 halves) per matrix per stage; 1 each
    int row = tid >> 1;
    int seg = tid & 1;
    int ra = m0 + row;
    if (EPI == 4) ra = min(ra, HWN - 1);
    const __half* ga = A + (size_t)ra * K + seg * 8;
    const __half* gb = Wt + (size_t)(n0 + row) * K + seg * 8;
    uint32_t aBase = smem_u32(&As[0][0][0]);
    uint32_t bBase = smem_u32(&Bs[0][0][0]);
    uint32_t asd = aBase + row * 48 + seg * 16;
    uint32_t bsd = bBase + row * 48 + seg * 16;

    // ldmatrix per-lane address offsets
    int alr = lane & 15;
    uint32_t aOff = (uint32_t)((wm * 64 + alr) * 48 + (lane >> 4) * 16);
    int blr = lane & 7;
    uint32_t bOff = (uint32_t)((wn * 32 + blr) * 48 + ((lane >> 3) & 1) * 16);

    int stages = K / 16;

    #pragma unroll
    for (int p = 0; p < 2; p++) {
        CP16(asd + p * STGB, ga + p * 16);
        CP16(bsd + p * STGB, gb + p * 16);
        asm volatile("cp.async.commit_group;");
    }

    for (int it = 0; it < stages; it++) {
        if (it + 2 < stages) {
            asm volatile("cp.async.wait_group 1;");
        } else {
            asm volatile("cp.async.wait_group 0;");
        }
        __syncthreads();
        if (it + 2 < stages) {
            int s = (it + 2) % NST;
            int k0 = (it + 2) * 16;
            CP16(asd + s * STGB, ga + k0);
            CP16(bsd + s * STGB, gb + k0);
            asm volatile("cp.async.commit_group;");
        }

        int s = it % NST;
        uint32_t sA = aBase + s * STGB + aOff;
        uint32_t sB = bBase + s * STGB + bOff;
        uint32_t a[4][4];
        #pragma unroll
        for (int mt = 0; mt < 4; mt++)
            LDSM_X4(a[mt][0], a[mt][1], a[mt][2], a[mt][3], sA + mt * (16 * 48));
        #pragma unroll
        for (int nt = 0; nt < 4; nt++) {
            uint32_t b0, b1;
            LDSM_X2(b0, b1, sB + nt * (8 * 48));
            #pragma unroll
            for (int mt = 0; mt < 4; mt++)
                MMA_H(acc[mt][nt], a[mt][0], a[mt][1], a[mt][2], a[mt][3], b0, b1);
        }
        __syncthreads();
    }

    float al = 0.f, cc = 0.f, ic = 0.f;
    if (EPI == 2) al = alphap[0];
    if (EPI == 4) { cc = U[0]; ic = 1.f / (cc + 1e-6f); }

    #pragma unroll
    for (int mt = 0; mt < 4; mt++) {
        int row0e = m0 + wm * 64 + mt * 16 + grp;
        #pragma unroll
        for (int nt = 0; nt < 4; nt++) {
            int col = n0 + wn * 32 + nt * 8 + qd * 2;
            float b0 = 0.f, b1 = 0.f;
            if (EPI != 2) { b0 = bias[col]; b1 = bias[col + 1]; }
            #pragma unroll
            for (int half = 0; half < 2; half++) {
                int r = row0e + half * 8;
                float v0 = acc[mt][nt][half * 2 + 0] + b0;
                float v1 = acc[mt][nt][half * 2 + 1] + b1;
                if (EPI == 0) {
                    if (col < 384)
                        *(float2*)&O0[(size_t)r * 384 + col] = make_float2(v0, v1);
                    else
                        *(float2*)&O1[(size_t)r * 384 + (col - 384)] = make_float2(v0, v1);
                } else if (EPI == 1) {
                    *(float2*)&O0[(size_t)r * N + col] = make_float2(v0, v1);
                } else if (EPI == 2) {
                    int ij = r % HWN;
                    int i = ij / 56, j = ij % 56;
                    float wnv = PI_F * i / 56.f, wmv = PI_F * j / 56.f;
                    float decay = expf(-(wnv * wnv + wmv * wmv));
                    float2 uv = *(const float2*)&U[(size_t)r * 384 + col];
                    float ua = uv.x * decay, ub = uv.y * decay;
                    float va = v0, vb = v1;
                    if (ij == 0) { va += 56.f * velb[col]; vb += 56.f * velb[col + 1]; }
                    va *= decay; vb *= decay;
                    float2 cv = *(const float2*)&cosb[(size_t)ij * 384 + col];
                    float2 sv = *(const float2*)&sinb[(size_t)ij * 384 + col];
                    float fa = cv.x * ua + sv.x * (va + 0.5f * al * ua);
                    float fb = cv.y * ub + sv.y * (vb + 0.5f * al * ub);
                    *(float2*)&O0[(size_t)r * 384 + col] = make_float2(fa, fb);
                } else if (EPI == 3) {
                    int b = r / HWN;
                    int ij = r - b * HWN;
                    size_t base = ((size_t)b * CCH + col) * HWN + ij;
                    O0[base] = v0;
                    O0[base + HWN] = v1;
                } else {  // EPI == 4
                    if (r < HWN) {
                        float t0 = fmaxf(v0, 0.f), t1v = fmaxf(v1, 0.f);
                        float a0 = cc * t0, a1 = cc * t1v;
                        *(float2*)&O0[(size_t)r * 384 + col] =
                            make_float2(cosf(a0), cosf(a1));
                        *(float2*)&O1[(size_t)r * 384 + col] =
                            make_float2(sinf(a0) * ic, sinf(a1) * ic);
                    }
                }
            }
        }
    }
}

// ---------------- tensor-core batched DCT stage (tf32 single-term) ----------------
// MODE 0: fp32 out (Of). MODE 1: fp16 out (Oh, feeds TC GEMM) + unrounded fp32 (O2).
template <int MODE>
__global__ void __launch_bounds__(256) dct_tc(const float* __restrict__ Dm, int transD,
                                              const float* __restrict__ X,
                                              float* __restrict__ Of,
                                              __half* __restrict__ Oh,
                                              float* __restrict__ O2, int N) {
    __shared__ float Ds[64][60];
    __shared__ float Xs[56][136];
    int tid = threadIdx.x;
    int g = blockIdx.y;
    int n0 = blockIdx.x * 128;

    for (int f = tid; f < 64 * 60; f += 256) {
        int i = f / 60, k = f - i * 60;
        float v = 0.f;
        if (i < 56 && k < 56)
            v = round_tf32(transD ? Dm[k * 56 + i] : Dm[i * 56 + k]);
        Ds[i][k] = v;
    }
    const float* Xg = X + (size_t)g * 56 * N + n0;
    for (int f = tid; f < 56 * 32; f += 256) {
        int h = f >> 5, n4 = (f & 31) * 4;
        float4 v = *(const float4*)(Xg + (size_t)h * N + n4);
        Xs[h][n4 + 0] = round_tf32(v.x);
        Xs[h][n4 + 1] = round_tf32(v.y);
        Xs[h][n4 + 2] = round_tf32(v.z);
        Xs[h][n4 + 3] = round_tf32(v.w);
    }
    __syncthreads();

    int warp = tid >> 5, lane = tid & 31;
    int grp = lane >> 2, qd = lane & 3;
    int nb = warp * 16;

    float acc[4][2][4];
    #pragma unroll
    for (int mt = 0; mt < 4; mt++)
        #pragma unroll
        for (int nt = 0; nt < 2; nt++)
            #pragma unroll
            for (int r = 0; r < 4; r++) acc[mt][nt][r] = 0.f;

    #pragma unroll
    for (int kc = 0; kc < 7; kc++) {
        int k0 = kc * 8;
        unsigned a[4][4];
        #pragma unroll
        for (int mt = 0; mt < 4; mt++) {
            int mrow = mt * 16 + grp;
            a[mt][0] = __float_as_uint(Ds[mrow][k0 + qd]);
            a[mt][1] = __float_as_uint(Ds[mrow + 8][k0 + qd]);
            a[mt][2] = __float_as_uint(Ds[mrow][k0 + qd + 4]);
            a[mt][3] = __float_as_uint(Ds[mrow + 8][k0 + qd + 4]);
        }
        #pragma unroll
        for (int nt = 0; nt < 2; nt++) {
            unsigned b0 = __float_as_uint(Xs[k0 + qd][nb + nt * 8 + grp]);
            unsigned b1 = __float_as_uint(Xs[k0 + qd + 4][nb + nt * 8 + grp]);
            #pragma unroll
            for (int mt = 0; mt < 4; mt++) {
                MMA_T(acc[mt][nt], a[mt][0], a[mt][1], a[mt][2], a[mt][3], b0, b1);
            }
        }
    }

    #pragma unroll
    for (int mt = 0; mt < 4; mt++) {
        #pragma unroll
        for (int half = 0; half < 2; half++) {
            int i = mt * 16 + grp + half * 8;
            if (i >= 56) continue;
            #pragma unroll
            for (int nt = 0; nt < 2; nt++) {
                int col = nb + nt * 8 + qd * 2;
                float v0 = acc[mt][nt][half * 2 + 0];
                float v1 = acc[mt][nt][half * 2 + 1];
                size_t off = (size_t)g * 56 * N + (size_t)i * N + n0 + col;
                if (MODE == 0) {
                    *(float2*)&Of[off] = make_float2(v0, v1);
                } else {
                    *(float2*)&O2[off] = make_float2(v0, v1);
                    __half2 hv = __floats2half2_rn(v0, v1);
                    *(__half2*)&Oh[off] = hv;
                }
            }
        }
    }
}

// ---------------- LayerNorm + SiLU gate -> fp16 ----------------
__global__ void ln_gate_k(const float* __restrict__ y, const float* __restrict__ z,
                          const float* __restrict__ g, const float* __restrict__ b,
                          __half* __restrict__ out) {
    int warp = threadIdx.x >> 5, lane = threadIdx.x & 31;
    size_t m = (size_t)blockIdx.x * 8 + warp;
    const float* yr = y + m * CCH;
    float vals[12];
    float s = 0.f;
    #pragma unroll
    for (int t = 0; t < 12; t++) { vals[t] = yr[lane + t * 32]; s += vals[t]; }
    #pragma unroll
    for (int o = 16; o > 0; o >>= 1) s += __shfl_xor_sync(0xffffffff, s, o);
    float mu = s * (1.f / 384.f);
    float q = 0.f;
    #pragma unroll
    for (int t = 0; t < 12; t++) { float d = vals[t] - mu; q += d * d; }
    #pragma unroll
    for (int o = 16; o > 0; o >>= 1) q += __shfl_xor_sync(0xffffffff, q, o);
    float rstd = rsqrtf(q * (1.f / 384.f) + 1e-5f);
    #pragma unroll
    for (int t = 0; t < 12; t++) {
        int c = lane + t * 32;
        float yn = (vals[t] - mu) * rstd * g[c] + b[c];
        float zz = z[m * CCH + c];
        out[m * CCH + c] = __float2half_rn(yn * (zz / (1.f + expf(-zz))));
    }
}

// ---------------- launch ----------------
extern "C" void kernel_launch(void* const* d_in, const int* in_sizes, int n_in,
                              void* d_out, int out_size) {
    const float* x          = (const float*)d_in[0];
    const float* freq_embed = (const float*)d_in[1];
    const float* dw_w       = (const float*)d_in[2];
    const float* dw_b       = (const float*)d_in[3];
    const float* lin_w      = (const float*)d_in[4];
    const float* lin_b      = (const float*)d_in[5];
    const float* vel_w      = (const float*)d_in[6];
    const float* vel_b      = (const float*)d_in[7];
    const float* tok_w      = (const float*)d_in[8];
    const float* tok_b      = (const float*)d_in[9];
    const float* ln_g       = (const float*)d_in[10];
    const float* ln_b       = (const float*)d_in[11];
    const float* out_w      = (const float*)d_in[12];
    const float* out_b      = (const float*)d_in[13];
    const float* cptr       = (const float*)d_in[14];
    const float* alphap     = (const float*)d_in[15];
    float* outp = (float*)d_out;

    float *xtF, *xg, *z, *t1, *u0, *v0, *cb, *sb, *Dm;
    __half *wlh, *wvh, *woh, *wth;
    cudaGetSymbolAddress((void**)&xtF, g_xt);
    cudaGetSymbolAddress((void**)&xg, g_xg);
    cudaGetSymbolAddress((void**)&z,  g_z);
    cudaGetSymbolAddress((void**)&t1, g_t1);
    cudaGetSymbolAddress((void**)&u0, g_u0);
    cudaGetSymbolAddress((void**)&v0, g_v0);
    cudaGetSymbolAddress((void**)&cb, g_cosb);
    cudaGetSymbolAddress((void**)&sb, g_sinb);
    cudaGetSymbolAddress((void**)&Dm, g_D);
    cudaGetSymbolAddress((void**)&wlh, g_wlh);
    cudaGetSymbolAddress((void**)&wvh, g_wvh);
    cudaGetSymbolAddress((void**)&woh, g_woh);
    cudaGetSymbolAddress((void**)&wth, g_wth);

    __half* xth = (__half*)xtF;      // fp16 activations (first half of g_xt)
    __half* u0h = (__half*)u0;       // fp16 u0
    __half* v0h = (__half*)v0;       // fp16 gated output
    __half* feh = (__half*)cb;       // fp16 freq_embed staging (cb written after)

    dct_init_k<<<13, 256>>>(Dm);                                      // 1
    cvtw_h<<<(768 * 384 + 255) / 256, 256>>>(lin_w, wlh, 768 * 384);  // 2
    dwconv_k<<<dim3(112, 48, 16), dim3(32, 8)>>>(x, dw_w, dw_b, xth); // 3
    cvtw_h<<<(384 * 384 + 255) / 256, 256>>>(vel_w, wvh, 384 * 384);  // 4
    cvtw_h<<<(384 * 384 + 255) / 256, 256>>>(out_w, woh, 384 * 384);  // 5

    // 6: xz = xt @ lin_w.T + lin_b ; split -> xg, z
    gemm_tc<0><<<dim3(6, MTOK / TBM), 256>>>(xth, wlh, lin_b, xg, z,
                                             nullptr, nullptr, nullptr, nullptr, nullptr,
                                             MTOK, 768, 384);

    cvtw_h<<<(384 * 384 + 255) / 256, 256>>>(tok_w, wth, 384 * 384);
    cvtw_h<<<(HWN * 384 + 255) / 256, 256>>>(freq_embed, feh, HWN * 384);

    // cos/sin tables (rows guarded to HWN); cptr passed as U  (feh dead after; cb/sb written)
    gemm_tc<4><<<dim3(3, 25), 256>>>(feh, wth, tok_b, cb, sb,
                                     cptr, nullptr, nullptr, nullptr, nullptr,
                                     3200, 384, 384);

    // u0 = DCT2(xg): stage1 fp32; stage2 dual-writes fp16 u0h + unrounded fp32 (g_xt)
    dct_tc<0><<<dim3(168, 16), 256>>>(Dm, 0, xg, t1, nullptr, nullptr, 21504);
    dct_tc<1><<<dim3(3, 896), 256>>>(Dm, 0, t1, nullptr, u0h, xtF, 384);

    // fin = mod(u0_unrounded, u0 @ vel_w.T) -> t1
    gemm_tc<2><<<dim3(3, MTOK / TBM), 256>>>(u0h, wvh, nullptr, t1, nullptr,
                                             xtF, cb, sb, vel_b, alphap,
                                             MTOK, 384, 384);

    // y = IDCT2(fin) -> u0 (fp32)
    dct_tc<0><<<dim3(168, 16), 256>>>(Dm, 1, t1, xg, nullptr, nullptr, 21504);
    dct_tc<0><<<dim3(3, 896), 256>>>(Dm, 1, xg, u0, nullptr, nullptr, 384);

    // LayerNorm + SiLU(z) gate -> v0h (fp16)
    ln_gate_k<<<MTOK / 8, 256>>>(u0, z, ln_g, ln_b, v0h);

    // out = gated @ out_w.T + out_b, written directly transposed to NCHW
    gemm_tc<3><<<dim3(3, MTOK / TBM), 256>>>(v0h, woh, out_b, outp, nullptr,
                                             nullptr, nullptr, nullptr, nullptr, nullptr,
                                             MTOK, 384, 384);
}

// round 15
// speedup vs baseline: 1.0099x; 1.0099x over previous
#include <cuda_runtime.h>
#include <cuda_fp16.h>
#include <math.h>
#include <stdint.h>

#define MTOK 50176
#define CCH 384
#define HWN 3136
#define PI_F 3.14159265358979323846f

// ---------------- scratch ----------------
__device__ float g_xt[(size_t)MTOK * CCH];
__device__ float g_xg[(size_t)MTOK * CCH];
__device__ float g_z [(size_t)MTOK * CCH];
__device__ float g_t1[(size_t)MTOK * CCH];
__device__ float g_u0[(size_t)MTOK * CCH];
__device__ float g_v0[(size_t)MTOK * CCH];
__device__ float g_cosb[(size_t)HWN * CCH];
__device__ float g_sinb[(size_t)HWN * CCH];
__device__ float g_D[56 * 56];
__device__ __half g_wlh[768 * 384];
__device__ __half g_wvh[384 * 384];
__device__ __half g_woh[384 * 384];
__device__ __half g_wth[384 * 384];

__device__ __forceinline__ unsigned f2tf32(float x) {
    unsigned r;
    asm("cvt.rna.tf32.f32 %0, %1;" : "=r"(r) : "f"(x));
    return r;
}
__device__ __forceinline__ float round_tf32(float x) {
    return __uint_as_float(f2tf32(x));
}
__device__ __forceinline__ uint32_t smem_u32(const void* p) {
    uint32_t a;
    asm("{ .reg .u64 t; cvta.to.shared.u64 t, %1; cvt.u32.u64 %0, t; }" : "=r"(a) : "l"(p));
    return a;
}
#define CP16(smaddr, gptr) \
    asm volatile("cp.async.ca.shared.global [%0], [%1], 16;" :: "r"(smaddr), "l"(gptr))

#define MMA_T(acc, a0, a1, a2, a3, b0, b1) \
    asm volatile( \
        "mma.sync.aligned.m16n8k8.row.col.f32.tf32.tf32.f32 " \
        "{%0,%1,%2,%3}, {%4,%5,%6,%7}, {%8,%9}, {%0,%1,%2,%3};" \
        : "+f"((acc)[0]), "+f"((acc)[1]), "+f"((acc)[2]), "+f"((acc)[3]) \
        : "r"(a0), "r"(a1), "r"(a2), "r"(a3), "r"(b0), "r"(b1))

#define MMA_H(acc, a0, a1, a2, a3, b0, b1) \
    asm volatile( \
        "mma.sync.aligned.m16n8k16.row.col.f32.f16.f16.f32 " \
        "{%0,%1,%2,%3}, {%4,%5,%6,%7}, {%8,%9}, {%0,%1,%2,%3};" \
        : "+f"((acc)[0]), "+f"((acc)[1]), "+f"((acc)[2]), "+f"((acc)[3]) \
        : "r"(a0), "r"(a1), "r"(a2), "r"(a3), "r"(b0), "r"(b1))

#define LDSM_X4(r0, r1, r2, r3, addr) \
    asm volatile("ldmatrix.sync.aligned.m8n8.x4.shared.b16 {%0,%1,%2,%3}, [%4];" \
        : "=r"(r0), "=r"(r1), "=r"(r2), "=r"(r3) : "r"(addr))

// non-trans: B stored [n][k]; lane i gets B[n=i/4][k=2(i%4)..] = exact mma b-fragment
#define LDSM_X2(r0, r1, addr) \
    asm volatile("ldmatrix.sync.aligned.m8n8.x2.shared.b16 {%0,%1}, [%2];" \
        : "=r"(r0), "=r"(r1) : "r"(addr))

// ---------------- weight pre-convert to fp16 ----------------
__global__ void cvtw_h(const float* __restrict__ in, __half* __restrict__ out, int n) {
    int i = blockIdx.x * 256 + threadIdx.x;
    if (i < n) out[i] = __float2half_rn(in[i]);
}

// ---------------- DCT matrix init ----------------
__global__ void dct_init_k(float* D) {
    int idx = blockIdx.x * 256 + threadIdx.x;
    if (idx < 56 * 56) {
        int k = idx / 56, n = idx % 56;
        double v = cos(3.14159265358979323846 * (2.0 * n + 1.0) * k / 112.0) * sqrt(2.0 / 56.0);
        if (k == 0) v *= (1.0 / sqrt(2.0));
        D[idx] = (float)v;
    }
}

// ---------------- depthwise 3x3 conv -> token-major fp16 ----------------
__global__ void dwconv_k(const float* __restrict__ x, const float* __restrict__ w,
                         const float* __restrict__ bias, __half* __restrict__ xt) {
    __shared__ float s[8][33];
    int tx = threadIdx.x, ty = threadIdx.y;
    int wseg = blockIdx.x & 1;
    int h = blockIdx.x >> 1;
    int c = blockIdx.y * 8 + ty;
    int b = blockIdx.z;
    int ww = wseg * 32 + tx;

    if (ww < 56) {
        float acc = bias[c];
        const float* xp = x + ((size_t)(b * CCH + c) * 56) * 56;
        const float* wp = w + c * 9;
        #pragma unroll
        for (int kh = 0; kh < 3; kh++) {
            int hh = h + kh - 1;
            if (hh < 0 || hh >= 56) continue;
            #pragma unroll
            for (int kw = 0; kw < 3; kw++) {
                int wc = ww + kw - 1;
                if (wc < 0 || wc >= 56) continue;
                acc += xp[hh * 56 + wc] * wp[kh * 3 + kw];
            }
        }
        s[ty][tx] = acc;
    }
    __syncthreads();
    int tid = ty * 32 + tx;
    int wi = tid >> 3, ci = tid & 7;
    int wo = wseg * 32 + wi;
    if (wo < 56) {
        int cout = blockIdx.y * 8 + ci;
        size_t tok = (size_t)b * HWN + h * 56 + wo;
        xt[tok * CCH + cout] = __float2half_rn(s[ci][wi]);
    }
}

// ---------------- FP16 TC GEMM: 8 warps x (64x32), ldmatrix, cp.async 3-stage ----------------
// A[M][K], Wt[N][K] fp16 (pre-converted). Smem rows padded to 24 halves (48B).
// EPI 0: +bias split -> O0/O1 ; 1: +bias -> O0 ; 2: wave mod ; 3: +bias transposed NCHW ;
// EPI 4: +bias relu cos/sin (U = cptr, rows guarded to HWN)
#define TBM 128
#define TBN 128
#define NST 3
#define HP 24                 // halves per smem row (48B)
#define STGB (128 * 48)       // bytes per stage per matrix

template <int EPI>
__global__ void __launch_bounds__(256, 2) gemm_tc(
    const __half* __restrict__ A, const __half* __restrict__ Wt,
    const float* __restrict__ bias,
    float* __restrict__ O0, float* __restrict__ O1,
    const float* __restrict__ U, const float* __restrict__ cosb,
    const float* __restrict__ sinb, const float* __restrict__ velb,
    const float* __restrict__ alphap,
    int M, int N, int K) {
    __shared__ __align__(16) __half As[NST][TBM][HP];
    __shared__ __align__(16) __half Bs[NST][TBN][HP];

    int tid = threadIdx.x;
    int lane = tid & 31;
    int warp = tid >> 5;
    int wm = warp & 1;
    int wn = warp >> 1;
    int m0 = blockIdx.y * TBM;
    int n0 = blockIdx.x * TBN;
    int grp = lane >> 2;
    int qd = lane & 3;

    float acc[4][4][4];
    #pragma unroll
    for (int i = 0; i < 4; i++)
        #pragma unroll
        for (int j = 0; j < 4; j++)
            #pragma unroll
            for (int r = 0; r < 4; r++) acc[i][j][r] = 0.f;

    // cp.async: 256 chunks of 16B (8 halves) per matrix per stage; 1 each
    int row = tid >> 1;
    int seg = tid & 1;
    int ra = m0 + row;
    if (EPI == 4) ra = min(ra, HWN - 1);
    const __half* ga = A + (size_t)ra * K + seg * 8;
    const __half* gb = Wt + (size_t)(n0 + row) * K + seg * 8;
    uint32_t aBase = smem_u32(&As[0][0][0]);
    uint32_t bBase = smem_u32(&Bs[0][0][0]);
    uint32_t asd = aBase + row * 48 + seg * 16;
    uint32_t bsd = bBase + row * 48 + seg * 16;

    // ldmatrix per-lane address offsets
    int alr = lane & 15;
    uint32_t aOff = (uint32_t)((wm * 64 + alr) * 48 + (lane >> 4) * 16);
    int blr = lane & 7;
    uint32_t bOff = (uint32_t)((wn * 32 + blr) * 48 + ((lane >> 3) & 1) * 16);

    int stages = K / 16;

    #pragma unroll
    for (int p = 0; p < 2; p++) {
        CP16(asd + p * STGB, ga + p * 16);
        CP16(bsd + p * STGB, gb + p * 16);
        asm volatile("cp.async.commit_group;");
    }

    for (int it = 0; it < stages; it++) {
        if (it + 2 < stages) {
            asm volatile("cp.async.wait_group 1;");
        } else {
            asm volatile("cp.async.wait_group 0;");
        }
        __syncthreads();
        if (it + 2 < stages) {
            int s = (it + 2) % NST;
            int k0 = (it + 2) * 16;
            CP16(asd + s * STGB, ga + k0);
            CP16(bsd + s * STGB, gb + k0);
            asm volatile("cp.async.commit_group;");
        }

        int s = it % NST;
        uint32_t sA = aBase + s * STGB + aOff;
        uint32_t sB = bBase + s * STGB + bOff;
        uint32_t a[4][4];
        #pragma unroll
        for (int mt = 0; mt < 4; mt++)
            LDSM_X4(a[mt][0], a[mt][1], a[mt][2], a[mt][3], sA + mt * (16 * 48));
        #pragma unroll
        for (int nt = 0; nt < 4; nt++) {
            uint32_t b0, b1;
            LDSM_X2(b0, b1, sB + nt * (8 * 48));
            #pragma unroll
            for (int mt = 0; mt < 4; mt++)
                MMA_H(acc[mt][nt], a[mt][0], a[mt][1], a[mt][2], a[mt][3], b0, b1);
        }
        __syncthreads();
    }

    float al = 0.f, cc = 0.f, ic = 0.f;
    if (EPI == 2) al = alphap[0];
    if (EPI == 4) { cc = U[0]; ic = 1.f / (cc + 1e-6f); }

    #pragma unroll
    for (int mt = 0; mt < 4; mt++) {
        int row0e = m0 + wm * 64 + mt * 16 + grp;
        #pragma unroll
        for (int nt = 0; nt < 4; nt++) {
            int col = n0 + wn * 32 + nt * 8 + qd * 2;
            float b0 = 0.f, b1 = 0.f;
            if (EPI != 2) { b0 = bias[col]; b1 = bias[col + 1]; }
            #pragma unroll
            for (int half = 0; half < 2; half++) {
                int r = row0e + half * 8;
                float v0 = acc[mt][nt][half * 2 + 0] + b0;
                float v1 = acc[mt][nt][half * 2 + 1] + b1;
                if (EPI == 0) {
                    if (col < 384)
                        *(float2*)&O0[(size_t)r * 384 + col] = make_float2(v0, v1);
                    else
                        *(float2*)&O1[(size_t)r * 384 + (col - 384)] = make_float2(v0, v1);
                } else if (EPI == 1) {
                    *(float2*)&O0[(size_t)r * N + col] = make_float2(v0, v1);
                } else if (EPI == 2) {
                    int ij = r % HWN;
                    int i = ij / 56, j = ij % 56;
                    float wnv = PI_F * i / 56.f, wmv = PI_F * j / 56.f;
                    float decay = expf(-(wnv * wnv + wmv * wmv));
                    float2 uv = *(const float2*)&U[(size_t)r * 384 + col];
                    float ua = uv.x * decay, ub = uv.y * decay;
                    float va = v0, vb = v1;
                    if (ij == 0) { va += 56.f * velb[col]; vb += 56.f * velb[col + 1]; }
                    va *= decay; vb *= decay;
                    float2 cv = *(const float2*)&cosb[(size_t)ij * 384 + col];
                    float2 sv = *(const float2*)&sinb[(size_t)ij * 384 + col];
                    float fa = cv.x * ua + sv.x * (va + 0.5f * al * ua);
                    float fb = cv.y * ub + sv.y * (vb + 0.5f * al * ub);
                    *(float2*)&O0[(size_t)r * 384 + col] = make_float2(fa, fb);
                } else if (EPI == 3) {
                    int b = r / HWN;
                    int ij = r - b * HWN;
                    size_t base = ((size_t)b * CCH + col) * HWN + ij;
                    O0[base] = v0;
                    O0[base + HWN] = v1;
                } else {  // EPI == 4
                    if (r < HWN) {
                        float t0 = fmaxf(v0, 0.f), t1v = fmaxf(v1, 0.f);
                        float a0 = cc * t0, a1 = cc * t1v;
                        *(float2*)&O0[(size_t)r * 384 + col] =
                            make_float2(cosf(a0), cosf(a1));
                        *(float2*)&O1[(size_t)r * 384 + col] =
                            make_float2(sinf(a0) * ic, sinf(a1) * ic);
                    }
                }
            }
        }
    }
}

// ---------------- tensor-core batched DCT stage (tf32 single-term) ----------------
// MODE 0: fp32 out (Of). MODE 1: fp16 out (Oh, feeds TC GEMM) + unrounded fp32 (O2).
template <int MODE>
__global__ void __launch_bounds__(256) dct_tc(const float* __restrict__ Dm, int transD,
                                              const float* __restrict__ X,
                                              float* __restrict__ Of,
                                              __half* __restrict__ Oh,
                                              float* __restrict__ O2, int N) {
    __shared__ float Ds[64][60];
    __shared__ float Xs[56][136];
    int tid = threadIdx.x;
    int g = blockIdx.y;
    int n0 = blockIdx.x * 128;

    for (int f = tid; f < 64 * 60; f += 256) {
        int i = f / 60, k = f - i * 60;
        float v = 0.f;
        if (i < 56 && k < 56)
            v = round_tf32(transD ? Dm[k * 56 + i] : Dm[i * 56 + k]);
        Ds[i][k] = v;
    }
    const float* Xg = X + (size_t)g * 56 * N + n0;
    for (int f = tid; f < 56 * 32; f += 256) {
        int h = f >> 5, n4 = (f & 31) * 4;
        float4 v = *(const float4*)(Xg + (size_t)h * N + n4);
        Xs[h][n4 + 0] = round_tf32(v.x);
        Xs[h][n4 + 1] = round_tf32(v.y);
        Xs[h][n4 + 2] = round_tf32(v.z);
        Xs[h][n4 + 3] = round_tf32(v.w);
    }
    __syncthreads();

    int warp = tid >> 5, lane = tid & 31;
    int grp = lane >> 2, qd = lane & 3;
    int nb = warp * 16;

    float acc[4][2][4];
    #pragma unroll
    for (int mt = 0; mt < 4; mt++)
        #pragma unroll
        for (int nt = 0; nt < 2; nt++)
            #pragma unroll
            for (int r = 0; r < 4; r++) acc[mt][nt][r] = 0.f;

    #pragma unroll
    for (int kc = 0; kc < 7; kc++) {
        int k0 = kc * 8;
        unsigned a[4][4];
        #pragma unroll
        for (int mt = 0; mt < 4; mt++) {
            int mrow = mt * 16 + grp;
            a[mt][0] = __float_as_uint(Ds[mrow][k0 + qd]);
            a[mt][1] = __float_as_uint(Ds[mrow + 8][k0 + qd]);
            a[mt][2] = __float_as_uint(Ds[mrow][k0 + qd + 4]);
            a[mt][3] = __float_as_uint(Ds[mrow + 8][k0 + qd + 4]);
        }
        #pragma unroll
        for (int nt = 0; nt < 2; nt++) {
            unsigned b0 = __float_as_uint(Xs[k0 + qd][nb + nt * 8 + grp]);
            unsigned b1 = __float_as_uint(Xs[k0 + qd + 4][nb + nt * 8 + grp]);
            #pragma unroll
            for (int mt = 0; mt < 4; mt++) {
                MMA_T(acc[mt][nt], a[mt][0], a[mt][1], a[mt][2], a[mt][3], b0, b1);
            }
        }
    }

    #pragma unroll
    for (int mt = 0; mt < 4; mt++) {
        #pragma unroll
        for (int half = 0; half < 2; half++) {
            int i = mt * 16 + grp + half * 8;
            if (i >= 56) continue;
            #pragma unroll
            for (int nt = 0; nt < 2; nt++) {
                int col = nb + nt * 8 + qd * 2;
                float v0 = acc[mt][nt][half * 2 + 0];
                float v1 = acc[mt][nt][half * 2 + 1];
                size_t off = (size_t)g * 56 * N + (size_t)i * N + n0 + col;
                if (MODE == 0) {
                    *(float2*)&Of[off] = make_float2(v0, v1);
                } else {
                    *(float2*)&O2[off] = make_float2(v0, v1);
                    __half2 hv = __floats2half2_rn(v0, v1);
                    *(__half2*)&Oh[off] = hv;
                }
            }
        }
    }
}

// ---------------- LayerNorm + SiLU gate -> fp16 ----------------
__global__ void ln_gate_k(const float* __restrict__ y, const float* __restrict__ z,
                          const float* __restrict__ g, const float* __restrict__ b,
                          __half* __restrict__ out) {
    int warp = threadIdx.x >> 5, lane = threadIdx.x & 31;
    size_t m = (size_t)blockIdx.x * 8 + warp;
    const float* yr = y + m * CCH;
    float vals[12];
    float s = 0.f;
    #pragma unroll
    for (int t = 0; t < 12; t++) { vals[t] = yr[lane + t * 32]; s += vals[t]; }
    #pragma unroll
    for (int o = 16; o > 0; o >>= 1) s += __shfl_xor_sync(0xffffffff, s, o);
    float mu = s * (1.f / 384.f);
    float q = 0.f;
    #pragma unroll
    for (int t = 0; t < 12; t++) { float d = vals[t] - mu; q += d * d; }
    #pragma unroll
    for (int o = 16; o > 0; o >>= 1) q += __shfl_xor_sync(0xffffffff, q, o);
    float rstd = rsqrtf(q * (1.f / 384.f) + 1e-5f);
    #pragma unroll
    for (int t = 0; t < 12; t++) {
        int c = lane + t * 32;
        float yn = (vals[t] - mu) * rstd * g[c] + b[c];
        float zz = z[m * CCH + c];
        out[m * CCH + c] = __float2half_rn(yn * (zz / (1.f + expf(-zz))));
    }
}

// ---------------- launch ----------------
extern "C" void kernel_launch(void* const* d_in, const int* in_sizes, int n_in,
                              void* d_out, int out_size) {
    const float* x          = (const float*)d_in[0];
    const float* freq_embed = (const float*)d_in[1];
    const float* dw_w       = (const float*)d_in[2];
    const float* dw_b       = (const float*)d_in[3];
    const float* lin_w      = (const float*)d_in[4];
    const float* lin_b      = (const float*)d_in[5];
    const float* vel_w      = (const float*)d_in[6];
    const float* vel_b      = (const float*)d_in[7];
    const float* tok_w      = (const float*)d_in[8];
    const float* tok_b      = (const float*)d_in[9];
    const float* ln_g       = (const float*)d_in[10];
    const float* ln_b       = (const float*)d_in[11];
    const float* out_w      = (const float*)d_in[12];
    const float* out_b      = (const float*)d_in[13];
    const float* cptr       = (const float*)d_in[14];
    const float* alphap     = (const float*)d_in[15];
    float* outp = (float*)d_out;

    float *xtF, *xg, *z, *t1, *u0, *v0, *cb, *sb, *Dm;
    __half *wlh, *wvh, *woh, *wth;
    cudaGetSymbolAddress((void**)&xtF, g_xt);
    cudaGetSymbolAddress((void**)&xg, g_xg);
    cudaGetSymbolAddress((void**)&z,  g_z);
    cudaGetSymbolAddress((void**)&t1, g_t1);
    cudaGetSymbolAddress((void**)&u0, g_u0);
    cudaGetSymbolAddress((void**)&v0, g_v0);
    cudaGetSymbolAddress((void**)&cb, g_cosb);
    cudaGetSymbolAddress((void**)&sb, g_sinb);
    cudaGetSymbolAddress((void**)&Dm, g_D);
    cudaGetSymbolAddress((void**)&wlh, g_wlh);
    cudaGetSymbolAddress((void**)&wvh, g_wvh);
    cudaGetSymbolAddress((void**)&woh, g_woh);
    cudaGetSymbolAddress((void**)&wth, g_wth);

    __half* xth = (__half*)xtF;      // fp16 activations (first half of g_xt)
    __half* u0h = (__half*)u0;       // fp16 u0
    __half* v0h = (__half*)v0;       // fp16 gated output
    __half* feh = (__half*)cb;       // fp16 freq_embed staging (cb written after)

    dct_init_k<<<13, 256>>>(Dm);                                      // 1
    cvtw_h<<<(768 * 384 + 255) / 256, 256>>>(lin_w, wlh, 768 * 384);  // 2
    dwconv_k<<<dim3(112, 48, 16), dim3(32, 8)>>>(x, dw_w, dw_b, xth); // 3
    cvtw_h<<<(384 * 384 + 255) / 256, 256>>>(vel_w, wvh, 384 * 384);  // 4
    cvtw_h<<<(384 * 384 + 255) / 256, 256>>>(out_w, woh, 384 * 384);  // 5

    // 6: xz = xt @ lin_w.T + lin_b ; split -> xg, z
    gemm_tc<0><<<dim3(6, MTOK / TBM), 256>>>(xth, wlh, lin_b, xg, z,
                                             nullptr, nullptr, nullptr, nullptr, nullptr,
                                             MTOK, 768, 384);

    cvtw_h<<<(384 * 384 + 255) / 256, 256>>>(tok_w, wth, 384 * 384);
    cvtw_h<<<(HWN * 384 + 255) / 256, 256>>>(freq_embed, feh, HWN * 384);

    // cos/sin tables (rows guarded to HWN); cptr passed as U  (feh dead after; cb/sb written)
    gemm_tc<4><<<dim3(3, 25), 256>>>(feh, wth, tok_b, cb, sb,
                                     cptr, nullptr, nullptr, nullptr, nullptr,
                                     3200, 384, 384);

    // u0 = DCT2(xg): stage1 fp32; stage2 dual-writes fp16 u0h + unrounded fp32 (g_xt)
    dct_tc<0><<<dim3(168, 16), 256>>>(Dm, 0, xg, t1, nullptr, nullptr, 21504);
    dct_tc<1><<<dim3(3, 896), 256>>>(Dm, 0, t1, nullptr, u0h, xtF, 384);

    // fin = mod(u0_unrounded, u0 @ vel_w.T) -> t1
    gemm_tc<2><<<dim3(3, MTOK / TBM), 256>>>(u0h, wvh, nullptr, t1, nullptr,
                                             xtF, cb, sb, vel_b, alphap,
                                             MTOK, 384, 384);

    // y = IDCT2(fin) -> u0 (fp32)
    dct_tc<0><<<dim3(168, 16), 256>>>(Dm, 1, t1, xg, nullptr, nullptr, 21504);
    dct_tc<0><<<dim3(3, 896), 256>>>(Dm, 1, xg, u0, nullptr, nullptr, 384);

    // LayerNorm + SiLU(z) gate -> v0h (fp16)
    ln_gate_k<<<MTOK / 8, 256>>>(u0, z, ln_g, ln_b, v0h);

    // out = gated @ out_w.T + out_b, written directly transposed to NCHW
    gemm_tc<3><<<dim3(3, MTOK / TBM), 256>>>(v0h, woh, out_b, outp, nullptr,
                                             nullptr, nullptr, nullptr, nullptr, nullptr,
                                             MTOK, 384, 384);
}

// round 16
// speedup vs baseline: 1.0939x; 1.0832x over previous
#include <cuda_runtime.h>
#include <cuda_fp16.h>
#include <math.h>
#include <stdint.h>

#define MTOK 50176
#define CCH 384
#define HWN 3136
#define PI_F 3.14159265358979323846f

// ---------------- scratch ----------------
__device__ float g_xt[(size_t)MTOK * CCH];
__device__ float g_xg[(size_t)MTOK * CCH];
__device__ float g_z [(size_t)MTOK * CCH];
__device__ float g_t1[(size_t)MTOK * CCH];
__device__ float g_u0[(size_t)MTOK * CCH];
__device__ float g_v0[(size_t)MTOK * CCH];
__device__ float g_cosb[(size_t)HWN * CCH];
__device__ float g_sinb[(size_t)HWN * CCH];
__device__ float g_D[56 * 56];
__device__ __half g_wlh[768 * 384];
__device__ __half g_wvh[384 * 384];
__device__ __half g_woh[384 * 384];
__device__ __half g_wth[384 * 384];

__device__ __forceinline__ unsigned f2tf32(float x) {
    unsigned r;
    asm("cvt.rna.tf32.f32 %0, %1;" : "=r"(r) : "f"(x));
    return r;
}
__device__ __forceinline__ float round_tf32(float x) {
    return __uint_as_float(f2tf32(x));
}
__device__ __forceinline__ uint32_t smem_u32(const void* p) {
    uint32_t a;
    asm("{ .reg .u64 t; cvta.to.shared.u64 t, %1; cvt.u32.u64 %0, t; }" : "=r"(a) : "l"(p));
    return a;
}
#define CP16(smaddr, gptr) \
    asm volatile("cp.async.ca.shared.global [%0], [%1], 16;" :: "r"(smaddr), "l"(gptr))

#define MMA_T(acc, a0, a1, a2, a3, b0, b1) \
    asm volatile( \
        "mma.sync.aligned.m16n8k8.row.col.f32.tf32.tf32.f32 " \
        "{%0,%1,%2,%3}, {%4,%5,%6,%7}, {%8,%9}, {%0,%1,%2,%3};" \
        : "+f"((acc)[0]), "+f"((acc)[1]), "+f"((acc)[2]), "+f"((acc)[3]) \
        : "r"(a0), "r"(a1), "r"(a2), "r"(a3), "r"(b0), "r"(b1))

#define MMA_H(acc, a0, a1, a2, a3, b0, b1) \
    asm volatile( \
        "mma.sync.aligned.m16n8k16.row.col.f32.f16.f16.f32 " \
        "{%0,%1,%2,%3}, {%4,%5,%6,%7}, {%8,%9}, {%0,%1,%2,%3};" \
        : "+f"((acc)[0]), "+f"((acc)[1]), "+f"((acc)[2]), "+f"((acc)[3]) \
        : "r"(a0), "r"(a1), "r"(a2), "r"(a3), "r"(b0), "r"(b1))

#define LDSM_X4(r0, r1, r2, r3, addr) \
    asm volatile("ldmatrix.sync.aligned.m8n8.x4.shared.b16 {%0,%1,%2,%3}, [%4];" \
        : "=r"(r0), "=r"(r1), "=r"(r2), "=r"(r3) : "r"(addr))

#define LDSM_X2(r0, r1, addr) \
    asm volatile("ldmatrix.sync.aligned.m8n8.x2.shared.b16 {%0,%1}, [%2];" \
        : "=r"(r0), "=r"(r1) : "r"(addr))

// ---------------- weight pre-convert to fp16 ----------------
__global__ void cvtw_h(const float* __restrict__ in, __half* __restrict__ out, int n) {
    int i = blockIdx.x * 256 + threadIdx.x;
    if (i < n) out[i] = __float2half_rn(in[i]);
}

// ---------------- DCT matrix init ----------------
__global__ void dct_init_k(float* D) {
    int idx = blockIdx.x * 256 + threadIdx.x;
    if (idx < 56 * 56) {
        int k = idx / 56, n = idx % 56;
        double v = cos(3.14159265358979323846 * (2.0 * n + 1.0) * k / 112.0) * sqrt(2.0 / 56.0);
        if (k == 0) v *= (1.0 / sqrt(2.0));
        D[idx] = (float)v;
    }
}

// ---------------- depthwise 3x3 conv -> token-major fp16 ----------------
__global__ void dwconv_k(const float* __restrict__ x, const float* __restrict__ w,
                         const float* __restrict__ bias, __half* __restrict__ xt) {
    __shared__ float s[8][33];
    int tx = threadIdx.x, ty = threadIdx.y;
    int wseg = blockIdx.x & 1;
    int h = blockIdx.x >> 1;
    int c = blockIdx.y * 8 + ty;
    int b = blockIdx.z;
    int ww = wseg * 32 + tx;

    if (ww < 56) {
        float acc = bias[c];
        const float* xp = x + ((size_t)(b * CCH + c) * 56) * 56;
        const float* wp = w + c * 9;
        #pragma unroll
        for (int kh = 0; kh < 3; kh++) {
            int hh = h + kh - 1;
            if (hh < 0 || hh >= 56) continue;
            #pragma unroll
            for (int kw = 0; kw < 3; kw++) {
                int wc = ww + kw - 1;
                if (wc < 0 || wc >= 56) continue;
                acc += xp[hh * 56 + wc] * wp[kh * 3 + kw];
            }
        }
        s[ty][tx] = acc;
    }
    __syncthreads();
    int tid = ty * 32 + tx;
    int wi = tid >> 3, ci = tid & 7;
    int wo = wseg * 32 + wi;
    if (wo < 56) {
        int cout = blockIdx.y * 8 + ci;
        size_t tok = (size_t)b * HWN + h * 56 + wo;
        xt[tok * CCH + cout] = __float2half_rn(s[ci][wi]);
    }
}

// ---------------- FP16 TC GEMM: 8 warps x (64x32), ldmatrix, cp.async 3-stage ----------------
// EPI 0: +bias split: n<384 -> fp16 O0 (xg) ; else fp32 O1 (z)
// EPI 2: wave mod; U fp16, output fp16 (fin)
// EPI 3: +bias, transposed fp32 NCHW
// EPI 4: +bias relu cos/sin (U = cptr, rows guarded to HWN)
#define TBM 128
#define TBN 128
#define NST 3
#define HP 24
#define STGB (128 * 48)

template <int EPI>
__global__ void __launch_bounds__(256, 2) gemm_tc(
    const __half* __restrict__ A, const __half* __restrict__ Wt,
    const float* __restrict__ bias,
    void* __restrict__ O0v, float* __restrict__ O1,
    const void* __restrict__ Uv, const float* __restrict__ cosb,
    const float* __restrict__ sinb, const float* __restrict__ velb,
    const float* __restrict__ alphap,
    int M, int N, int K) {
    __shared__ __align__(16) __half As[NST][TBM][HP];
    __shared__ __align__(16) __half Bs[NST][TBN][HP];

    int tid = threadIdx.x;
    int lane = tid & 31;
    int warp = tid >> 5;
    int wm = warp & 1;
    int wn = warp >> 1;
    int m0 = blockIdx.y * TBM;
    int n0 = blockIdx.x * TBN;
    int grp = lane >> 2;
    int qd = lane & 3;

    float acc[4][4][4];
    #pragma unroll
    for (int i = 0; i < 4; i++)
        #pragma unroll
        for (int j = 0; j < 4; j++)
            #pragma unroll
            for (int r = 0; r < 4; r++) acc[i][j][r] = 0.f;

    int row = tid >> 1;
    int seg = tid & 1;
    int ra = m0 + row;
    if (EPI == 4) ra = min(ra, HWN - 1);
    const __half* ga = A + (size_t)ra * K + seg * 8;
    const __half* gb = Wt + (size_t)(n0 + row) * K + seg * 8;
    uint32_t aBase = smem_u32(&As[0][0][0]);
    uint32_t bBase = smem_u32(&Bs[0][0][0]);
    uint32_t asd = aBase + row * 48 + seg * 16;
    uint32_t bsd = bBase + row * 48 + seg * 16;

    int alr = lane & 15;
    uint32_t aOff = (uint32_t)((wm * 64 + alr) * 48 + (lane >> 4) * 16);
    int blr = lane & 7;
    uint32_t bOff = (uint32_t)((wn * 32 + blr) * 48 + ((lane >> 3) & 1) * 16);

    int stages = K / 16;

    #pragma unroll
    for (int p = 0; p < 2; p++) {
        CP16(asd + p * STGB, ga + p * 16);
        CP16(bsd + p * STGB, gb + p * 16);
        asm volatile("cp.async.commit_group;");
    }

    for (int it = 0; it < stages; it++) {
        if (it + 2 < stages) {
            asm volatile("cp.async.wait_group 1;");
        } else {
            asm volatile("cp.async.wait_group 0;");
        }
        __syncthreads();
        if (it + 2 < stages) {
            int s = (it + 2) % NST;
            int k0 = (it + 2) * 16;
            CP16(asd + s * STGB, ga + k0);
            CP16(bsd + s * STGB, gb + k0);
            asm volatile("cp.async.commit_group;");
        }

        int s = it % NST;
        uint32_t sA = aBase + s * STGB + aOff;
        uint32_t sB = bBase + s * STGB + bOff;
        uint32_t a[4][4];
        #pragma unroll
        for (int mt = 0; mt < 4; mt++)
            LDSM_X4(a[mt][0], a[mt][1], a[mt][2], a[mt][3], sA + mt * (16 * 48));
        #pragma unroll
        for (int nt = 0; nt < 4; nt++) {
            uint32_t b0, b1;
            LDSM_X2(b0, b1, sB + nt * (8 * 48));
            #pragma unroll
            for (int mt = 0; mt < 4; mt++)
                MMA_H(acc[mt][nt], a[mt][0], a[mt][1], a[mt][2], a[mt][3], b0, b1);
        }
        __syncthreads();
    }

    float al = 0.f, cc = 0.f, ic = 0.f;
    if (EPI == 2) al = alphap[0];
    if (EPI == 4) { cc = ((const float*)Uv)[0]; ic = 1.f / (cc + 1e-6f); }

    float* O0f = (float*)O0v;
    __half* O0h = (__half*)O0v;
    const __half* Uh = (const __half*)Uv;

    #pragma unroll
    for (int mt = 0; mt < 4; mt++) {
        int row0e = m0 + wm * 64 + mt * 16 + grp;
        #pragma unroll
        for (int nt = 0; nt < 4; nt++) {
            int col = n0 + wn * 32 + nt * 8 + qd * 2;
            float b0 = 0.f, b1 = 0.f;
            if (EPI != 2) { b0 = bias[col]; b1 = bias[col + 1]; }
            #pragma unroll
            for (int half = 0; half < 2; half++) {
                int r = row0e + half * 8;
                float v0 = acc[mt][nt][half * 2 + 0] + b0;
                float v1 = acc[mt][nt][half * 2 + 1] + b1;
                if (EPI == 0) {
                    if (col < 384)
                        *(__half2*)&O0h[(size_t)r * 384 + col] = __floats2half2_rn(v0, v1);
                    else
                        *(float2*)&O1[(size_t)r * 384 + (col - 384)] = make_float2(v0, v1);
                } else if (EPI == 2) {
                    int ij = r % HWN;
                    int i = ij / 56, j = ij % 56;
                    float wnv = PI_F * i / 56.f, wmv = PI_F * j / 56.f;
                    float decay = expf(-(wnv * wnv + wmv * wmv));
                    float2 uv = __half22float2(*(const __half2*)&Uh[(size_t)r * 384 + col]);
                    float ua = uv.x * decay, ub = uv.y * decay;
                    float va = v0, vb = v1;
                    if (ij == 0) { va += 56.f * velb[col]; vb += 56.f * velb[col + 1]; }
                    va *= decay; vb *= decay;
                    float2 cv = *(const float2*)&cosb[(size_t)ij * 384 + col];
                    float2 sv = *(const float2*)&sinb[(size_t)ij * 384 + col];
                    float fa = cv.x * ua + sv.x * (va + 0.5f * al * ua);
                    float fb = cv.y * ub + sv.y * (vb + 0.5f * al * ub);
                    *(__half2*)&O0h[(size_t)r * 384 + col] = __floats2half2_rn(fa, fb);
                } else if (EPI == 3) {
                    int b = r / HWN;
                    int ij = r - b * HWN;
                    size_t base = ((size_t)b * CCH + col) * HWN + ij;
                    O0f[base] = v0;
                    O0f[base + HWN] = v1;
                } else {  // EPI == 4
                    if (r < HWN) {
                        float t0 = fmaxf(v0, 0.f), t1v = fmaxf(v1, 0.f);
                        float a0 = cc * t0, a1 = cc * t1v;
                        *(float2*)&O0f[(size_t)r * 384 + col] =
                            make_float2(cosf(a0), cosf(a1));
                        *(float2*)&O1[(size_t)r * 384 + col] =
                            make_float2(sinf(a0) * ic, sinf(a1) * ic);
                    }
                }
            }
        }
    }
}

// ---------------- tensor-core batched DCT stage (tf32 single-term) ----------------
// INH: input is fp16 (exact cvt to fp32, already on tf32 grid). OUTH: fp16 output.
template <int INH, int OUTH>
__global__ void __launch_bounds__(256) dct_tc(const float* __restrict__ Dm, int transD,
                                              const void* __restrict__ Xv,
                                              void* __restrict__ Ov, int N) {
    __shared__ float Ds[64][60];
    __shared__ float Xs[56][136];
    int tid = threadIdx.x;
    int g = blockIdx.y;
    int n0 = blockIdx.x * 128;

    for (int f = tid; f < 64 * 60; f += 256) {
        int i = f / 60, k = f - i * 60;
        float v = 0.f;
        if (i < 56 && k < 56)
            v = round_tf32(transD ? Dm[k * 56 + i] : Dm[i * 56 + k]);
        Ds[i][k] = v;
    }
    for (int f = tid; f < 56 * 32; f += 256) {
        int h = f >> 5, n4 = (f & 31) * 4;
        if (INH) {
            const __half* Xg = (const __half*)Xv + (size_t)g * 56 * N + n0;
            __half2 p0 = *(const __half2*)(Xg + (size_t)h * N + n4);
            __half2 p1 = *(const __half2*)(Xg + (size_t)h * N + n4 + 2);
            float2 f0 = __half22float2(p0), f1 = __half22float2(p1);
            Xs[h][n4 + 0] = f0.x; Xs[h][n4 + 1] = f0.y;
            Xs[h][n4 + 2] = f1.x; Xs[h][n4 + 3] = f1.y;
        } else {
            const float* Xg = (const float*)Xv + (size_t)g * 56 * N + n0;
            float4 v = *(const float4*)(Xg + (size_t)h * N + n4);
            Xs[h][n4 + 0] = round_tf32(v.x);
            Xs[h][n4 + 1] = round_tf32(v.y);
            Xs[h][n4 + 2] = round_tf32(v.z);
            Xs[h][n4 + 3] = round_tf32(v.w);
        }
    }
    __syncthreads();

    int warp = tid >> 5, lane = tid & 31;
    int grp = lane >> 2, qd = lane & 3;
    int nb = warp * 16;

    float acc[4][2][4];
    #pragma unroll
    for (int mt = 0; mt < 4; mt++)
        #pragma unroll
        for (int nt = 0; nt < 2; nt++)
            #pragma unroll
            for (int r = 0; r < 4; r++) acc[mt][nt][r] = 0.f;

    #pragma unroll
    for (int kc = 0; kc < 7; kc++) {
        int k0 = kc * 8;
        unsigned a[4][4];
        #pragma unroll
        for (int mt = 0; mt < 4; mt++) {
            int mrow = mt * 16 + grp;
            a[mt][0] = __float_as_uint(Ds[mrow][k0 + qd]);
            a[mt][1] = __float_as_uint(Ds[mrow + 8][k0 + qd]);
            a[mt][2] = __float_as_uint(Ds[mrow][k0 + qd + 4]);
            a[mt][3] = __float_as_uint(Ds[mrow + 8][k0 + qd + 4]);
        }
        #pragma unroll
        for (int nt = 0; nt < 2; nt++) {
            unsigned b0 = __float_as_uint(Xs[k0 + qd][nb + nt * 8 + grp]);
            unsigned b1 = __float_as_uint(Xs[k0 + qd + 4][nb + nt * 8 + grp]);
            #pragma unroll
            for (int mt = 0; mt < 4; mt++) {
                MMA_T(acc[mt][nt], a[mt][0], a[mt][1], a[mt][2], a[mt][3], b0, b1);
            }
        }
    }

    #pragma unroll
    for (int mt = 0; mt < 4; mt++) {
        #pragma unroll
        for (int half = 0; half < 2; half++) {
            int i = mt * 16 + grp + half * 8;
            if (i >= 56) continue;
            #pragma unroll
            for (int nt = 0; nt < 2; nt++) {
                int col = nb + nt * 8 + qd * 2;
                float v0 = acc[mt][nt][half * 2 + 0];
                float v1 = acc[mt][nt][half * 2 + 1];
                size_t off = (size_t)g * 56 * N + (size_t)i * N + n0 + col;
                if (OUTH) {
                    *(__half2*)((__half*)Ov + off) = __floats2half2_rn(v0, v1);
                } else {
                    *(float2*)((float*)Ov + off) = make_float2(v0, v1);
                }
            }
        }
    }
}

// ---------------- LayerNorm + SiLU gate -> fp16 ----------------
__global__ void ln_gate_k(const float* __restrict__ y, const float* __restrict__ z,
                          const float* __restrict__ g, const float* __restrict__ b,
                          __half* __restrict__ out) {
    int warp = threadIdx.x >> 5, lane = threadIdx.x & 31;
    size_t m = (size_t)blockIdx.x * 8 + warp;
    const float* yr = y + m * CCH;
    float vals[12];
    float s = 0.f;
    #pragma unroll
    for (int t = 0; t < 12; t++) { vals[t] = yr[lane + t * 32]; s += vals[t]; }
    #pragma unroll
    for (int o = 16; o > 0; o >>= 1) s += __shfl_xor_sync(0xffffffff, s, o);
    float mu = s * (1.f / 384.f);
    float q = 0.f;
    #pragma unroll
    for (int t = 0; t < 12; t++) { float d = vals[t] - mu; q += d * d; }
    #pragma unroll
    for (int o = 16; o > 0; o >>= 1) q += __shfl_xor_sync(0xffffffff, q, o);
    float rstd = rsqrtf(q * (1.f / 384.f) + 1e-5f);
    #pragma unroll
    for (int t = 0; t < 12; t++) {
        int c = lane + t * 32;
        float yn = (vals[t] - mu) * rstd * g[c] + b[c];
        float zz = z[m * CCH + c];
        out[m * CCH + c] = __float2half_rn(yn * (zz / (1.f + expf(-zz))));
    }
}

// ---------------- launch ----------------
extern "C" void kernel_launch(void* const* d_in, const int* in_sizes, int n_in,
                              void* d_out, int out_size) {
    const float* x          = (const float*)d_in[0];
    const float* freq_embed = (const float*)d_in[1];
    const float* dw_w       = (const float*)d_in[2];
    const float* dw_b       = (const float*)d_in[3];
    const float* lin_w      = (const float*)d_in[4];
    const float* lin_b      = (const float*)d_in[5];
    const float* vel_w      = (const float*)d_in[6];
    const float* vel_b      = (const float*)d_in[7];
    const float* tok_w      = (const float*)d_in[8];
    const float* tok_b      = (const float*)d_in[9];
    const float* ln_g       = (const float*)d_in[10];
    const float* ln_b       = (const float*)d_in[11];
    const float* out_w      = (const float*)d_in[12];
    const float* out_b      = (const float*)d_in[13];
    const float* cptr       = (const float*)d_in[14];
    const float* alphap     = (const float*)d_in[15];
    float* outp = (float*)d_out;

    float *xtF, *xg, *z, *t1, *u0, *v0, *cb, *sb, *Dm;
    __half *wlh, *wvh, *woh, *wth;
    cudaGetSymbolAddress((void**)&xtF, g_xt);
    cudaGetSymbolAddress((void**)&xg, g_xg);
    cudaGetSymbolAddress((void**)&z,  g_z);
    cudaGetSymbolAddress((void**)&t1, g_t1);
    cudaGetSymbolAddress((void**)&u0, g_u0);
    cudaGetSymbolAddress((void**)&v0, g_v0);
    cudaGetSymbolAddress((void**)&cb, g_cosb);
    cudaGetSymbolAddress((void**)&sb, g_sinb);
    cudaGetSymbolAddress((void**)&Dm, g_D);
    cudaGetSymbolAddress((void**)&wlh, g_wlh);
    cudaGetSymbolAddress((void**)&wvh, g_wvh);
    cudaGetSymbolAddress((void**)&woh, g_woh);
    cudaGetSymbolAddress((void**)&wth, g_wth);

    __half* xth = (__half*)xtF;      // fp16 conv output
    __half* xgh = (__half*)xg;       // fp16 xg / IDCT stage-1 scratch
    __half* t1h = (__half*)t1;       // fp16 DCT stage-1 out / fin
    __half* u0h = (__half*)u0;       // fp16 u0 (dead before s4 writes fp32 u0)
    __half* v0h = (__half*)v0;       // fp16 gated output
    __half* feh = (__half*)cb;       // fp16 freq_embed staging (cb written after)

    dct_init_k<<<13, 256>>>(Dm);                                      // 1
    cvtw_h<<<(768 * 384 + 255) / 256, 256>>>(lin_w, wlh, 768 * 384);  // 2
    dwconv_k<<<dim3(112, 48, 16), dim3(32, 8)>>>(x, dw_w, dw_b, xth); // 3
    cvtw_h<<<(384 * 384 + 255) / 256, 256>>>(vel_w, wvh, 384 * 384);  // 4
    cvtw_h<<<(384 * 384 + 255) / 256, 256>>>(out_w, woh, 384 * 384);  // 5

    // 6: xz = xt @ lin_w.T + lin_b ; split -> xg (fp16), z (fp32)
    gemm_tc<0><<<dim3(6, MTOK / TBM), 256>>>(xth, wlh, lin_b, xgh, z,
                                             nullptr, nullptr, nullptr, nullptr, nullptr,
                                             MTOK, 768, 384);

    cvtw_h<<<(384 * 384 + 255) / 256, 256>>>(tok_w, wth, 384 * 384);
    cvtw_h<<<(HWN * 384 + 255) / 256, 256>>>(freq_embed, feh, HWN * 384);

    // cos/sin tables (rows guarded to HWN); cptr passed as U
    gemm_tc<4><<<dim3(3, 25), 256>>>(feh, wth, tok_b, cb, sb,
                                     cptr, nullptr, nullptr, nullptr, nullptr,
                                     3200, 384, 384);

    // u0 = DCT2(xg): fp16 in/out both stages
    dct_tc<1, 1><<<dim3(168, 16), 256>>>(Dm, 0, xgh, t1h, 21504);
    dct_tc<1, 1><<<dim3(3, 896), 256>>>(Dm, 0, t1h, u0h, 384);

    // fin = mod(u0h, u0 @ vel_w.T) -> t1h (fp16); U = u0h
    gemm_tc<2><<<dim3(3, MTOK / TBM), 256>>>(u0h, wvh, nullptr, t1h, nullptr,
                                             u0h, cb, sb, vel_b, alphap,
                                             MTOK, 384, 384);

    // y = IDCT2(fin): s3 fp16->fp16 (xgh), s4 fp16->fp32 (u0)
    dct_tc<1, 1><<<dim3(168, 16), 256>>>(Dm, 1, t1h, xgh, 21504);
    dct_tc<1, 0><<<dim3(3, 896), 256>>>(Dm, 1, xgh, u0, 384);

    // LayerNorm + SiLU(z) gate -> v0h (fp16)
    ln_gate_k<<<MTOK / 8, 256>>>(u0, z, ln_g, ln_b, v0h);

    // out = gated @ out_w.T + out_b, written directly transposed to NCHW
    gemm_tc<3><<<dim3(3, MTOK / TBM), 256>>>(v0h, woh, out_b, outp, nullptr,
                                             nullptr, nullptr, nullptr, nullptr, nullptr,
                                             MTOK, 384, 384);
}